// round 4
// baseline (speedup 1.0000x reference)
#include <cuda_runtime.h>
#include <cuda_bf16.h>
#include <mma.h>
#include <cstdint>

using namespace nvcuda;

#define BATCH 16
#define DMODEL 1024
#define DM2 512
#define LSZ 4096
#define SS 64

// ---- scratch (device globals; no allocations allowed) ----
__device__ float g_bcdt[BATCH * SS * LSZ];   // pre-conv BCdt   (16 MB)
__device__ float g_conv[BATCH * SS * LSZ];   // conv output v   (16 MB)
__device__ float g_AB[BATCH * SS * LSZ];     // softmax * c0*v  (16 MB)
__device__ float g_ypre[BATCH * DM2 * LSZ];  // y before final conv (128 MB)

// packed fp32x2 FMA (Blackwell)
__device__ __forceinline__ float2 ffma2(float2 a, float2 b, float2 c) {
    unsigned long long ua = *reinterpret_cast<unsigned long long*>(&a);
    unsigned long long ub = *reinterpret_cast<unsigned long long*>(&b);
    unsigned long long uc = *reinterpret_cast<unsigned long long*>(&c);
    unsigned long long ud;
    asm("fma.rn.f32x2 %0, %1, %2, %3;" : "=l"(ud) : "l"(ua), "l"(ub), "l"(uc));
    return *reinterpret_cast<float2*>(&ud);
}
__device__ __forceinline__ float2 dup2(float v) { return make_float2(v, v); }

// ============================================================
// k1: BCdt[b,s,l] = sum_d xh[b,d,l] * w_bcdt[s,d] + b_bcdt[s]
// ============================================================
__global__ void k1_gemm(const float* __restrict__ x,
                        const float* __restrict__ w,
                        const float* __restrict__ bias) {
    __shared__ __align__(16) float Ws[32][68];
    __shared__ __align__(16) float Xs[32][128];
    int b = blockIdx.y;
    int l0 = blockIdx.x * 128;
    int tid = threadIdx.x;
    int tx = tid & 15;   // l: tx*8
    int ty = tid >> 4;   // s: ty*4

    float2 acc[4][4];
#pragma unroll
    for (int i = 0; i < 4; i++)
#pragma unroll
        for (int j = 0; j < 4; j++) acc[i][j] = make_float2(0.f, 0.f);

    const float* xb = x + (size_t)b * DMODEL * LSZ;

    for (int kc = 0; kc < DM2; kc += 32) {
#pragma unroll
        for (int k = 0; k < 8; k++) {
            int e = tid + k * 256;
            int s = e >> 5, kq = e & 31;
            Ws[kq][s] = w[s * DM2 + kc + kq];
        }
#pragma unroll
        for (int k = 0; k < 16; k++) {
            int e = tid + k * 256;
            int kr = e >> 7, l = e & 127;
            Xs[kr][l] = xb[(size_t)(kc + kr) * LSZ + l0 + l];
        }
        __syncthreads();
#pragma unroll
        for (int kk = 0; kk < 32; kk++) {
            const float4* xp = reinterpret_cast<const float4*>(&Xs[kk][tx * 8]);
            float4 xa = xp[0], xb4 = xp[1];
            float2 xv[4] = { make_float2(xa.x, xa.y), make_float2(xa.z, xa.w),
                             make_float2(xb4.x, xb4.y), make_float2(xb4.z, xb4.w) };
            float4 wq = *reinterpret_cast<const float4*>(&Ws[kk][ty * 4]);
            float wv[4] = { wq.x, wq.y, wq.z, wq.w };
#pragma unroll
            for (int i = 0; i < 4; i++) {
                float2 wp = dup2(wv[i]);
#pragma unroll
                for (int j = 0; j < 4; j++)
                    acc[i][j] = ffma2(wp, xv[j], acc[i][j]);
            }
        }
        __syncthreads();
    }
#pragma unroll
    for (int i = 0; i < 4; i++) {
        int s = ty * 4 + i;
        float bv = bias[s];
        float* op = &g_bcdt[((size_t)b * SS + s) * LSZ + l0 + tx * 8];
        float4 o0 = make_float4(acc[i][0].x + bv, acc[i][0].y + bv,
                                acc[i][1].x + bv, acc[i][1].y + bv);
        float4 o1 = make_float4(acc[i][2].x + bv, acc[i][2].y + bv,
                                acc[i][3].x + bv, acc[i][3].y + bv);
        *(float4*)op = o0;
        *(float4*)(op + 4) = o1;
    }
}

// ============================================================
// k2: per (b,s) plane: conv3x3 + softmax; g_conv = v, g_AB = sm*c0*v
// ============================================================
__global__ void k2_conv_softmax(const float* __restrict__ wdw,
                                const float* __restrict__ bdw,
                                const float* __restrict__ A,
                                const float* __restrict__ coeffs) {
    __shared__ float sm[66][68];
    __shared__ float red[8];
    int s = blockIdx.x, b = blockIdx.y;
    int tid = threadIdx.x;
    size_t off = ((size_t)b * SS + s) * LSZ;
    const float* plane = g_bcdt + off;

    for (int e = tid; e < 66 * 68; e += 256) ((float*)sm)[e] = 0.f;
    __syncthreads();
#pragma unroll
    for (int k = 0; k < 16; k++) {
        int idx = tid + k * 256;
        sm[(idx >> 6) + 1][(idx & 63) + 1] = plane[idx];
    }
    __syncthreads();

    float w[9];
#pragma unroll
    for (int i = 0; i < 9; i++) w[i] = wdw[s * 9 + i];
    float bb = bdw[s];
    float c0 = coeffs[0], c2 = coeffs[2];
    float Av = A[s];

    float v[16];
    float lmax = -1e30f;
#pragma unroll
    for (int k = 0; k < 16; k++) {
        int idx = tid + k * 256;
        int r = idx >> 6, c = idx & 63;
        float acc = bb;
#pragma unroll
        for (int i = 0; i < 3; i++)
#pragma unroll
            for (int j = 0; j < 3; j++)
                acc += w[i * 3 + j] * sm[r + i][c + j];
        v[k] = acc;
        lmax = fmaxf(lmax, c2 * acc + Av);
    }
#pragma unroll
    for (int o = 16; o > 0; o >>= 1)
        lmax = fmaxf(lmax, __shfl_xor_sync(0xffffffffu, lmax, o));
    if ((tid & 31) == 0) red[tid >> 5] = lmax;
    __syncthreads();
    float bmax = red[0];
#pragma unroll
    for (int i = 1; i < 8; i++) bmax = fmaxf(bmax, red[i]);
    __syncthreads();

    float ev[16];
    float lsum = 0.f;
#pragma unroll
    for (int k = 0; k < 16; k++) {
        ev[k] = __expf(c2 * v[k] + Av - bmax);
        lsum += ev[k];
    }
#pragma unroll
    for (int o = 16; o > 0; o >>= 1)
        lsum += __shfl_xor_sync(0xffffffffu, lsum, o);
    if ((tid & 31) == 0) red[tid >> 5] = lsum;
    __syncthreads();
    float bsum = 0.f;
#pragma unroll
    for (int i = 0; i < 8; i++) bsum += red[i];
    float inv = 1.f / bsum;

#pragma unroll
    for (int k = 0; k < 16; k++) {
        int idx = tid + k * 256;
        g_conv[off + idx] = v[k];
        g_AB[off + idx] = ev[k] * inv * c0 * v[k];
    }
}

// ============================================================
// k3: h[b,d,s] = sum_l xh[b,d,l] * AB[b,s,l]; split-K=8, atomics
// ============================================================
__global__ void k3_h(const float* __restrict__ x, float* __restrict__ hout) {
    __shared__ __align__(16) float Xs[32][132];  // [l][d]
    __shared__ __align__(16) float Bs[32][68];   // [l][s]
    int lp = blockIdx.x;
    int d0 = blockIdx.y * 128;
    int b = blockIdx.z;
    int tid = threadIdx.x;
    int tx = tid & 7;    // s: tx*8
    int ty = tid >> 3;   // d: ty*4

    float2 acc[4][4];
#pragma unroll
    for (int i = 0; i < 4; i++)
#pragma unroll
        for (int j = 0; j < 4; j++) acc[i][j] = make_float2(0.f, 0.f);

    const float* xb = x + ((size_t)b * DMODEL + d0) * LSZ + lp * 512;
    const float* ab = g_AB + (size_t)b * SS * LSZ + lp * 512;

    for (int lc = 0; lc < 512; lc += 32) {
#pragma unroll
        for (int k = 0; k < 16; k++) {
            int e = tid + k * 256;
            int l = e & 31, dd = e >> 5;
            Xs[l][dd] = xb[(size_t)dd * LSZ + lc + l];
        }
#pragma unroll
        for (int k = 0; k < 8; k++) {
            int e = tid + k * 256;
            int l = e & 31, si = e >> 5;
            Bs[l][si] = ab[(size_t)si * LSZ + lc + l];
        }
        __syncthreads();
#pragma unroll
        for (int l = 0; l < 32; l++) {
            const float4* bp = reinterpret_cast<const float4*>(&Bs[l][tx * 8]);
            float4 b0 = bp[0], b1 = bp[1];
            float2 bv[4] = { make_float2(b0.x, b0.y), make_float2(b0.z, b0.w),
                             make_float2(b1.x, b1.y), make_float2(b1.z, b1.w) };
            float4 xq = *reinterpret_cast<const float4*>(&Xs[l][ty * 4]);
            float xv4[4] = { xq.x, xq.y, xq.z, xq.w };
#pragma unroll
            for (int i = 0; i < 4; i++) {
                float2 xv = dup2(xv4[i]);
#pragma unroll
                for (int j = 0; j < 4; j++)
                    acc[i][j] = ffma2(xv, bv[j], acc[i][j]);
            }
        }
        __syncthreads();
    }
    float* hb = hout + ((size_t)b * DM2 + d0) * SS;
#pragma unroll
    for (int i = 0; i < 4; i++) {
        float* row = &hb[(ty * 4 + i) * SS + tx * 8];
#pragma unroll
        for (int j = 0; j < 4; j++) {
            atomicAdd(row + j * 2, acc[i][j].x);
            atomicAdd(row + j * 2 + 1, acc[i][j].y);
        }
    }
}

// ============================================================
// k4a (wmma/bf16 split): y_pre[128d x 128l] = sum_64s (c1*h)[d,s]*conv[s,l]
// 3-term split: Ahi*Bhi + Ahi*Blo + Alo*Bhi, fp32 accum.
// smem tiles: Ahi/Alo [128][80] bf16, Bhi/Blo [64][144] bf16.
// epilogue stage [128][136] fp32 reuses tile memory.
// ============================================================
#define A_LD 80
#define B_LD 144
#define ST_LD 136
#define OFF_AHI 0
#define OFF_ALO (128 * A_LD * 2)                 // 20480
#define OFF_BHI (2 * 128 * A_LD * 2)             // 40960
#define OFF_BLO (OFF_BHI + 64 * B_LD * 2)        // 59392
#define K4A_SMEM (OFF_BLO + 64 * B_LD * 2)       // 77824

__global__ void __launch_bounds__(256, 1) k4a_y_wmma(const float* __restrict__ hin,
                                                     const float* __restrict__ coeffs) {
    extern __shared__ __align__(256) char smem[];
    __nv_bfloat16* Ahi = reinterpret_cast<__nv_bfloat16*>(smem + OFF_AHI);
    __nv_bfloat16* Alo = reinterpret_cast<__nv_bfloat16*>(smem + OFF_ALO);
    __nv_bfloat16* Bhi = reinterpret_cast<__nv_bfloat16*>(smem + OFF_BHI);
    __nv_bfloat16* Blo = reinterpret_cast<__nv_bfloat16*>(smem + OFF_BLO);

    int l0 = blockIdx.x * 128;
    int d0 = blockIdx.y * 128;
    int b = blockIdx.z;
    int tid = threadIdx.x;
    int wid = tid >> 5;
    float c1 = coeffs[1];

    // ---- fill A: (d,s) = c1*h[d0+d][s], bf16 hi/lo split ----
    const float* hb = hin + ((size_t)b * DM2 + d0) * SS;
#pragma unroll
    for (int k = 0; k < 32; k++) {
        int e = tid + k * 256;            // 8192 = 128d x 64s (s fast)
        int d = e >> 6, s = e & 63;
        float v = c1 * hb[e];
        __nv_bfloat16 hi = __float2bfloat16_rn(v);
        __nv_bfloat16 lo = __float2bfloat16_rn(v - __bfloat162float(hi));
        Ahi[d * A_LD + s] = hi;
        Alo[d * A_LD + s] = lo;
    }
    // ---- fill B: (s,l) = conv[s][l0+l], bf16 hi/lo split ----
    const float* cb = g_conv + (size_t)b * SS * LSZ + l0;
#pragma unroll
    for (int k = 0; k < 32; k++) {
        int e = tid + k * 256;            // 8192 = 64s x 128l (l fast: coalesced)
        int s = e >> 7, l = e & 127;
        float v = cb[(size_t)s * LSZ + l];
        __nv_bfloat16 hi = __float2bfloat16_rn(v);
        __nv_bfloat16 lo = __float2bfloat16_rn(v - __bfloat162float(hi));
        Bhi[s * B_LD + l] = hi;
        Blo[s * B_LD + l] = lo;
    }
    __syncthreads();

    // ---- wmma mainloop: warp tile 32d x 64l ----
    int wd = (wid >> 1) * 32;   // 0,32,64,96
    int wl = (wid & 1) * 64;    // 0,64

    wmma::fragment<wmma::accumulator, 16, 16, 16, float> acc[2][4];
#pragma unroll
    for (int i = 0; i < 2; i++)
#pragma unroll
        for (int j = 0; j < 4; j++) wmma::fill_fragment(acc[i][j], 0.f);

#pragma unroll
    for (int ks = 0; ks < 4; ks++) {
        int k = ks * 16;
        wmma::fragment<wmma::matrix_a, 16, 16, 16, __nv_bfloat16, wmma::row_major> ah[2], al[2];
        wmma::fragment<wmma::matrix_b, 16, 16, 16, __nv_bfloat16, wmma::row_major> bh[4], bl[4];
#pragma unroll
        for (int i = 0; i < 2; i++) {
            wmma::load_matrix_sync(ah[i], Ahi + (wd + i * 16) * A_LD + k, A_LD);
            wmma::load_matrix_sync(al[i], Alo + (wd + i * 16) * A_LD + k, A_LD);
        }
#pragma unroll
        for (int j = 0; j < 4; j++) {
            wmma::load_matrix_sync(bh[j], Bhi + k * B_LD + wl + j * 16, B_LD);
            wmma::load_matrix_sync(bl[j], Blo + k * B_LD + wl + j * 16, B_LD);
        }
#pragma unroll
        for (int i = 0; i < 2; i++)
#pragma unroll
            for (int j = 0; j < 4; j++) {
                wmma::mma_sync(acc[i][j], ah[i], bh[j], acc[i][j]);
                wmma::mma_sync(acc[i][j], ah[i], bl[j], acc[i][j]);
                wmma::mma_sync(acc[i][j], al[i], bh[j], acc[i][j]);
            }
    }
    __syncthreads();   // tiles dead; reuse as fp32 stage

    float* stage = reinterpret_cast<float*>(smem);
#pragma unroll
    for (int i = 0; i < 2; i++)
#pragma unroll
        for (int j = 0; j < 4; j++)
            wmma::store_matrix_sync(stage + (wd + i * 16) * ST_LD + wl + j * 16,
                                    acc[i][j], ST_LD, wmma::mem_row_major);
    __syncthreads();

    // ---- coalesced gmem stores: 128 rows x 32 float4 ----
    const float4* st4 = reinterpret_cast<const float4*>(stage);
#pragma unroll
    for (int k = 0; k < 16; k++) {
        int g = tid + k * 256;            // 4096 float4 groups
        int row = g >> 5, c4 = g & 31;
        float4 v = st4[row * (ST_LD / 4) + c4];
        *reinterpret_cast<float4*>(
            &g_ypre[((size_t)b * DM2 + d0 + row) * LSZ + l0 + c4 * 4]) = v;
    }
}

// ============================================================
// k4b: final depthwise conv over 1024 channels.
// ============================================================
__global__ void k4b_conv(const float* __restrict__ x,
                         const float* __restrict__ wDW,
                         const float* __restrict__ bDW,
                         float* __restrict__ out) {
    __shared__ float sm[66][68];
    int c = blockIdx.x, b = blockIdx.y;
    int tid = threadIdx.x;
    const float* plane = (c < DM2)
        ? (g_ypre + ((size_t)b * DM2 + c) * LSZ)
        : (x + ((size_t)b * DMODEL + c) * LSZ);

    for (int e = tid; e < 66 * 68; e += 256) ((float*)sm)[e] = 0.f;
    __syncthreads();
#pragma unroll
    for (int k = 0; k < 16; k++) {
        int idx = tid + k * 256;
        sm[(idx >> 6) + 1][(idx & 63) + 1] = plane[idx];
    }
    __syncthreads();

    float w[9];
#pragma unroll
    for (int i = 0; i < 9; i++) w[i] = wDW[c * 9 + i];
    float bb = bDW[c];
    float* ob = out + ((size_t)b * DMODEL + c) * LSZ;
#pragma unroll
    for (int k = 0; k < 16; k++) {
        int idx = tid + k * 256;
        int r = idx >> 6, cc = idx & 63;
        float acc = bb;
#pragma unroll
        for (int i = 0; i < 3; i++)
#pragma unroll
            for (int j = 0; j < 3; j++)
                acc += w[i * 3 + j] * sm[r + i][cc + j];
        ob[idx] = acc;
    }
}

// ============================================================
extern "C" void kernel_launch(void* const* d_in, const int* in_sizes, int n_in,
                              void* d_out, int out_size) {
    const float* x      = (const float*)d_in[0];
    const float* w_bcdt = (const float*)d_in[1];
    const float* b_bcdt = (const float*)d_in[2];
    const float* w_dw   = (const float*)d_in[3];
    const float* b_dw   = (const float*)d_in[4];
    const float* A      = (const float*)d_in[5];
    const float* coeffs = (const float*)d_in[6];
    const float* w_DW   = (const float*)d_in[7];
    const float* b_DW   = (const float*)d_in[8];

    float* y_out = (float*)d_out;                          // (16,1024,4096)
    float* h_out = y_out + (size_t)BATCH * DMODEL * LSZ;   // (16,512,64)

    cudaFuncSetAttribute(k4a_y_wmma, cudaFuncAttributeMaxDynamicSharedMemorySize, K4A_SMEM);

    cudaMemsetAsync(h_out, 0, (size_t)BATCH * DM2 * SS * sizeof(float));

    k1_gemm<<<dim3(32, 16), 256>>>(x, w_bcdt, b_bcdt);
    k2_conv_softmax<<<dim3(64, 16), 256>>>(w_dw, b_dw, A, coeffs);
    k3_h<<<dim3(8, 4, 16), 256>>>(x, h_out);
    k4a_y_wmma<<<dim3(32, 4, 16), 256, K4A_SMEM>>>(h_out, coeffs);
    k4b_conv<<<dim3(1024, 16), 256>>>(x, w_DW, b_DW, y_out);
}

// round 5
// speedup vs baseline: 1.6176x; 1.6176x over previous
#include <cuda_runtime.h>
#include <cuda_bf16.h>
#include <mma.h>
#include <cstdint>

using namespace nvcuda;

#define BATCH 16
#define DMODEL 1024
#define DM2 512
#define LSZ 4096
#define SS 64

// ---- scratch (device globals; no allocations allowed) ----
__device__ float g_bcdt[BATCH * SS * LSZ];                 // 16 MB fp32
__device__ __nv_bfloat16 g_conv_hi[BATCH * SS * LSZ];      // 8 MB
__device__ __nv_bfloat16 g_conv_lo[BATCH * SS * LSZ];
__device__ __nv_bfloat16 g_AB_hi[BATCH * SS * LSZ];
__device__ __nv_bfloat16 g_AB_lo[BATCH * SS * LSZ];
__device__ __nv_bfloat16 g_xh_hi[BATCH * DM2 * LSZ];       // 64 MB
__device__ __nv_bfloat16 g_xh_lo[BATCH * DM2 * LSZ];
__device__ __nv_bfloat16 g_w_hi[SS * DM2];
__device__ __nv_bfloat16 g_w_lo[SS * DM2];
__device__ __nv_bfloat16 g_h_hi[BATCH * DM2 * SS];         // c1-scaled
__device__ __nv_bfloat16 g_h_lo[BATCH * DM2 * SS];
__device__ float g_ypre[BATCH * DM2 * LSZ];                // 128 MB

__device__ __forceinline__ uint32_t pk(__nv_bfloat16 a, __nv_bfloat16 b) {
    __nv_bfloat162 t; t.x = a; t.y = b;
    return *reinterpret_cast<uint32_t*>(&t);
}
__device__ __forceinline__ void split1(float v, __nv_bfloat16& hi, __nv_bfloat16& lo) {
    hi = __float2bfloat16_rn(v);
    lo = __float2bfloat16_rn(v - __bfloat162float(hi));
}

// ============================================================
// k0: xh (first 512 rows of x) -> bf16 hi/lo. 8.39M float4.
// ============================================================
__global__ void k0_convert_x(const float4* __restrict__ x4) {
    int tid = threadIdx.x;
#pragma unroll
    for (int k = 0; k < 16; k++) {
        int g = blockIdx.x * 4096 + k * 256 + tid;          // f4 index in xh space
        float4 v = x4[((size_t)(g >> 19) << 20) + (g & 0x7FFFF)];
        __nv_bfloat16 h0, l0, h1, l1, h2, l2, h3, l3;
        split1(v.x, h0, l0); split1(v.y, h1, l1);
        split1(v.z, h2, l2); split1(v.w, h3, l3);
        uint2 hv = make_uint2(pk(h0, h1), pk(h2, h3));
        uint2 lv = make_uint2(pk(l0, l1), pk(l2, l3));
        *reinterpret_cast<uint2*>(&g_xh_hi[(size_t)g * 4]) = hv;
        *reinterpret_cast<uint2*>(&g_xh_lo[(size_t)g * 4]) = lv;
    }
}
__global__ void k0_convert_w(const float4* __restrict__ w4) {
    int tid = threadIdx.x;
#pragma unroll
    for (int k = 0; k < 4; k++) {
        int g = blockIdx.x * 1024 + k * 256 + tid;          // 8192 f4
        float4 v = w4[g];
        __nv_bfloat16 h0, l0, h1, l1, h2, l2, h3, l3;
        split1(v.x, h0, l0); split1(v.y, h1, l1);
        split1(v.z, h2, l2); split1(v.w, h3, l3);
        *reinterpret_cast<uint2*>(&g_w_hi[g * 4]) = make_uint2(pk(h0, h1), pk(h2, h3));
        *reinterpret_cast<uint2*>(&g_w_lo[g * 4]) = make_uint2(pk(l0, l1), pk(l2, l3));
    }
}

// ============================================================
// k1 (wmma): BCdt[s,l] = sum_d w[s,d]*xh[d,l] + bias[s]
// block: 64s x 128l, K=512 chunks of 64. grid (32, 16b).
// ============================================================
#define K1_WLD 72
#define K1_XLD 136
#define K1_OFF_WHI 0
#define K1_OFF_WLO 9216
#define K1_OFF_XHI 18432
#define K1_OFF_XLO 35840
#define K1_SMEM 53248

__global__ void k1_wmma(const float* __restrict__ bias) {
    extern __shared__ __align__(16) char smem[];
    __nv_bfloat16* Whi = reinterpret_cast<__nv_bfloat16*>(smem + K1_OFF_WHI);
    __nv_bfloat16* Wlo = reinterpret_cast<__nv_bfloat16*>(smem + K1_OFF_WLO);
    __nv_bfloat16* Xhi = reinterpret_cast<__nv_bfloat16*>(smem + K1_OFF_XHI);
    __nv_bfloat16* Xlo = reinterpret_cast<__nv_bfloat16*>(smem + K1_OFF_XLO);
    int b = blockIdx.y;
    int l0 = blockIdx.x * 128;
    int tid = threadIdx.x;
    int wid = tid >> 5;
    int wm = (wid >> 1) * 16;    // s
    int wn = (wid & 1) * 64;     // l

    wmma::fragment<wmma::accumulator, 16, 16, 16, float> acc[4];
#pragma unroll
    for (int j = 0; j < 4; j++) wmma::fill_fragment(acc[j], 0.f);

    for (int kc = 0; kc < DM2; kc += 64) {
        // W chunk: 64s x 64k (hi+lo), 1024 uint2 each
#pragma unroll
        for (int k = 0; k < 4; k++) {
            int e = tid + k * 256;
            int s = e >> 4, q = e & 15;
            *reinterpret_cast<uint2*>(&Whi[s * K1_WLD + q * 4]) =
                *reinterpret_cast<const uint2*>(&g_w_hi[s * DM2 + kc + q * 4]);
            *reinterpret_cast<uint2*>(&Wlo[s * K1_WLD + q * 4]) =
                *reinterpret_cast<const uint2*>(&g_w_lo[s * DM2 + kc + q * 4]);
        }
        // X chunk: 64k x 128l, 2048 uint2 each
#pragma unroll
        for (int k = 0; k < 8; k++) {
            int e = tid + k * 256;
            int r = e >> 5, q = e & 31;
            size_t src = (((size_t)b * DM2 + kc + r) << 12) + l0 + q * 4;
            *reinterpret_cast<uint2*>(&Xhi[r * K1_XLD + q * 4]) =
                *reinterpret_cast<const uint2*>(&g_xh_hi[src]);
            *reinterpret_cast<uint2*>(&Xlo[r * K1_XLD + q * 4]) =
                *reinterpret_cast<const uint2*>(&g_xh_lo[src]);
        }
        __syncthreads();
#pragma unroll
        for (int ks = 0; ks < 4; ks++) {
            int kk = ks * 16;
            wmma::fragment<wmma::matrix_a, 16, 16, 16, __nv_bfloat16, wmma::row_major> ah, al;
            wmma::load_matrix_sync(ah, Whi + wm * K1_WLD + kk, K1_WLD);
            wmma::load_matrix_sync(al, Wlo + wm * K1_WLD + kk, K1_WLD);
#pragma unroll
            for (int j = 0; j < 4; j++) {
                wmma::fragment<wmma::matrix_b, 16, 16, 16, __nv_bfloat16, wmma::row_major> bh, bl;
                wmma::load_matrix_sync(bh, Xhi + kk * K1_XLD + wn + j * 16, K1_XLD);
                wmma::load_matrix_sync(bl, Xlo + kk * K1_XLD + wn + j * 16, K1_XLD);
                wmma::mma_sync(acc[j], ah, bh, acc[j]);
                wmma::mma_sync(acc[j], ah, bl, acc[j]);
                wmma::mma_sync(acc[j], al, bh, acc[j]);
            }
        }
        __syncthreads();
    }
    float* stage = reinterpret_cast<float*>(smem);          // [64][136]
#pragma unroll
    for (int j = 0; j < 4; j++)
        wmma::store_matrix_sync(stage + wm * K1_XLD + wn + j * 16, acc[j],
                                K1_XLD, wmma::mem_row_major);
    __syncthreads();
#pragma unroll
    for (int k = 0; k < 8; k++) {
        int g = tid + k * 256;              // 2048 f4 = 64 rows x 32
        int row = g >> 5, c4 = g & 31;
        float bv = bias[row];
        float4 v = *reinterpret_cast<const float4*>(&stage[row * K1_XLD + c4 * 4]);
        v.x += bv; v.y += bv; v.z += bv; v.w += bv;
        *reinterpret_cast<float4*>(
            &g_bcdt[((size_t)b * SS + row) * LSZ + l0 + c4 * 4]) = v;
    }
}

// ============================================================
// k2: conv3x3 + softmax; writes bf16 hi/lo of conv and AB.
// ============================================================
__global__ void k2_conv_softmax(const float* __restrict__ wdw,
                                const float* __restrict__ bdw,
                                const float* __restrict__ A,
                                const float* __restrict__ coeffs) {
    __shared__ float sm[66][68];
    __shared__ float red[8];
    int s = blockIdx.x, b = blockIdx.y;
    int tid = threadIdx.x;
    size_t off = ((size_t)b * SS + s) * LSZ;
    const float* plane = g_bcdt + off;

    for (int e = tid; e < 66 * 68; e += 256) ((float*)sm)[e] = 0.f;
    __syncthreads();
#pragma unroll
    for (int k = 0; k < 16; k++) {
        int idx = tid + k * 256;
        sm[(idx >> 6) + 1][(idx & 63) + 1] = plane[idx];
    }
    __syncthreads();

    float w[9];
#pragma unroll
    for (int i = 0; i < 9; i++) w[i] = wdw[s * 9 + i];
    float bb = bdw[s];
    float c0 = coeffs[0], c2 = coeffs[2];
    float Av = A[s];

    float v[16];
    float lmax = -1e30f;
#pragma unroll
    for (int k = 0; k < 8; k++) {
        int base = tid * 2 + k * 512;       // even; pair stays in one row
        int r = base >> 6, c = base & 63;
        float a0 = bb, a1 = bb;
#pragma unroll
        for (int i = 0; i < 3; i++)
#pragma unroll
            for (int j = 0; j < 3; j++) {
                float wv = w[i * 3 + j];
                a0 += wv * sm[r + i][c + j];
                a1 += wv * sm[r + i][c + 1 + j];
            }
        v[2 * k] = a0; v[2 * k + 1] = a1;
        lmax = fmaxf(lmax, fmaxf(c2 * a0, c2 * a1) + Av);
    }
#pragma unroll
    for (int o = 16; o > 0; o >>= 1)
        lmax = fmaxf(lmax, __shfl_xor_sync(0xffffffffu, lmax, o));
    if ((tid & 31) == 0) red[tid >> 5] = lmax;
    __syncthreads();
    float bmax = red[0];
#pragma unroll
    for (int i = 1; i < 8; i++) bmax = fmaxf(bmax, red[i]);
    __syncthreads();

    float ev[16];
    float lsum = 0.f;
#pragma unroll
    for (int k = 0; k < 16; k++) {
        ev[k] = __expf(c2 * v[k] + Av - bmax);
        lsum += ev[k];
    }
#pragma unroll
    for (int o = 16; o > 0; o >>= 1)
        lsum += __shfl_xor_sync(0xffffffffu, lsum, o);
    if ((tid & 31) == 0) red[tid >> 5] = lsum;
    __syncthreads();
    float bsum = 0.f;
#pragma unroll
    for (int i = 0; i < 8; i++) bsum += red[i];
    float inv = 1.f / bsum;

#pragma unroll
    for (int k = 0; k < 8; k++) {
        int base = tid * 2 + k * 512;
        float v0 = v[2 * k], v1 = v[2 * k + 1];
        __nv_bfloat16 ch0, cl0, ch1, cl1;
        split1(v0, ch0, cl0); split1(v1, ch1, cl1);
        *reinterpret_cast<uint32_t*>(&g_conv_hi[off + base]) = pk(ch0, ch1);
        *reinterpret_cast<uint32_t*>(&g_conv_lo[off + base]) = pk(cl0, cl1);
        float a0 = ev[2 * k] * inv * c0 * v0;
        float a1 = ev[2 * k + 1] * inv * c0 * v1;
        __nv_bfloat16 ah0, al0, ah1, al1;
        split1(a0, ah0, al0); split1(a1, ah1, al1);
        *reinterpret_cast<uint32_t*>(&g_AB_hi[off + base]) = pk(ah0, ah1);
        *reinterpret_cast<uint32_t*>(&g_AB_lo[off + base]) = pk(al0, al1);
    }
}

// ============================================================
// k3 (wmma): h[d,s] = sum_l xh[d,l]*AB[s,l]
// block: 128d x 64s, L-split 4 (1024 each), chunks of 64; atomics out.
// ============================================================
#define K3_ALD 72
#define K3_BLD 72
#define K3_OFF_AHI 0
#define K3_OFF_ALO 18432
#define K3_OFF_BHI 36864
#define K3_OFF_BLO 46080
#define K3_SMEM 55296

__global__ void k3_wmma(float* __restrict__ hout) {
    extern __shared__ __align__(16) char smem[];
    __nv_bfloat16* Ahi = reinterpret_cast<__nv_bfloat16*>(smem + K3_OFF_AHI);
    __nv_bfloat16* Alo = reinterpret_cast<__nv_bfloat16*>(smem + K3_OFF_ALO);
    __nv_bfloat16* Bhi = reinterpret_cast<__nv_bfloat16*>(smem + K3_OFF_BHI);
    __nv_bfloat16* Blo = reinterpret_cast<__nv_bfloat16*>(smem + K3_OFF_BLO);
    int lp = blockIdx.x;                 // 0..3
    int d0 = blockIdx.y * 128;
    int b = blockIdx.z;
    int tid = threadIdx.x;
    int wid = tid >> 5;
    int wm = (wid >> 1) * 32;            // d
    int wn = (wid & 1) * 32;             // s

    wmma::fragment<wmma::accumulator, 16, 16, 16, float> acc[2][2];
#pragma unroll
    for (int i = 0; i < 2; i++)
#pragma unroll
        for (int j = 0; j < 2; j++) wmma::fill_fragment(acc[i][j], 0.f);

    for (int lc = 0; lc < 1024; lc += 64) {
        int lbase = lp * 1024 + lc;
#pragma unroll
        for (int k = 0; k < 8; k++) {        // A: 128d x 64l, 2048 u2 each
            int e = tid + k * 256;
            int d = e >> 4, q = e & 15;
            size_t src = (((size_t)b * DM2 + d0 + d) << 12) + lbase + q * 4;
            *reinterpret_cast<uint2*>(&Ahi[d * K3_ALD + q * 4]) =
                *reinterpret_cast<const uint2*>(&g_xh_hi[src]);
            *reinterpret_cast<uint2*>(&Alo[d * K3_ALD + q * 4]) =
                *reinterpret_cast<const uint2*>(&g_xh_lo[src]);
        }
#pragma unroll
        for (int k = 0; k < 4; k++) {        // B: 64s x 64l, 1024 u2 each
            int e = tid + k * 256;
            int si = e >> 4, q = e & 15;
            size_t src = (((size_t)b * SS + si) << 12) + lbase + q * 4;
            *reinterpret_cast<uint2*>(&Bhi[si * K3_BLD + q * 4]) =
                *reinterpret_cast<const uint2*>(&g_AB_hi[src]);
            *reinterpret_cast<uint2*>(&Blo[si * K3_BLD + q * 4]) =
                *reinterpret_cast<const uint2*>(&g_AB_lo[src]);
        }
        __syncthreads();
#pragma unroll
        for (int ks = 0; ks < 4; ks++) {
            int kk = ks * 16;
            wmma::fragment<wmma::matrix_a, 16, 16, 16, __nv_bfloat16, wmma::row_major> ah[2], al[2];
            wmma::fragment<wmma::matrix_b, 16, 16, 16, __nv_bfloat16, wmma::col_major> bh[2], bl[2];
#pragma unroll
            for (int i = 0; i < 2; i++) {
                wmma::load_matrix_sync(ah[i], Ahi + (wm + i * 16) * K3_ALD + kk, K3_ALD);
                wmma::load_matrix_sync(al[i], Alo + (wm + i * 16) * K3_ALD + kk, K3_ALD);
            }
#pragma unroll
            for (int j = 0; j < 2; j++) {
                wmma::load_matrix_sync(bh[j], Bhi + (wn + j * 16) * K3_BLD + kk, K3_BLD);
                wmma::load_matrix_sync(bl[j], Blo + (wn + j * 16) * K3_BLD + kk, K3_BLD);
            }
#pragma unroll
            for (int i = 0; i < 2; i++)
#pragma unroll
                for (int j = 0; j < 2; j++) {
                    wmma::mma_sync(acc[i][j], ah[i], bh[j], acc[i][j]);
                    wmma::mma_sync(acc[i][j], ah[i], bl[j], acc[i][j]);
                    wmma::mma_sync(acc[i][j], al[i], bh[j], acc[i][j]);
                }
        }
        __syncthreads();
    }
    float* stage = reinterpret_cast<float*>(smem);          // [128][72]
#pragma unroll
    for (int i = 0; i < 2; i++)
#pragma unroll
        for (int j = 0; j < 2; j++)
            wmma::store_matrix_sync(stage + (wm + i * 16) * K3_ALD + wn + j * 16,
                                    acc[i][j], K3_ALD, wmma::mem_row_major);
    __syncthreads();
    float* hb = hout + ((size_t)b * DM2 + d0) * SS;
#pragma unroll
    for (int k = 0; k < 32; k++) {
        int e = tid + k * 256;               // 8192 = 128d x 64s
        int d = e >> 6, si = e & 63;
        atomicAdd(&hb[d * SS + si], stage[d * K3_ALD + si]);
    }
}

// ============================================================
// k3b: h fp32 -> bf16 hi/lo with c1 folded in. 131072 f4.
// ============================================================
__global__ void k3b_convert_h(const float4* __restrict__ h4,
                              const float* __restrict__ coeffs) {
    float c1 = coeffs[1];
    int tid = threadIdx.x;
#pragma unroll
    for (int k = 0; k < 4; k++) {
        int g = blockIdx.x * 1024 + k * 256 + tid;
        float4 v = h4[g];
        v.x *= c1; v.y *= c1; v.z *= c1; v.w *= c1;
        __nv_bfloat16 h0, l0, h1, l1, h2, l2, h3, l3;
        split1(v.x, h0, l0); split1(v.y, h1, l1);
        split1(v.z, h2, l2); split1(v.w, h3, l3);
        *reinterpret_cast<uint2*>(&g_h_hi[(size_t)g * 4]) = make_uint2(pk(h0, h1), pk(h2, h3));
        *reinterpret_cast<uint2*>(&g_h_lo[(size_t)g * 4]) = make_uint2(pk(l0, l1), pk(l2, l3));
    }
}

// ============================================================
// k4a (wmma): y_pre[d,l] = sum_s (c1*h)[d,s]*conv[s,l]
// block: 128d x 64l, K=64. grid (64 l, 4 d, 16 b).
// ============================================================
__global__ void k4a_wmma() {
    extern __shared__ __align__(16) char smem[];
    __nv_bfloat16* Ahi = reinterpret_cast<__nv_bfloat16*>(smem + K3_OFF_AHI);
    __nv_bfloat16* Alo = reinterpret_cast<__nv_bfloat16*>(smem + K3_OFF_ALO);
    __nv_bfloat16* Bhi = reinterpret_cast<__nv_bfloat16*>(smem + K3_OFF_BHI);
    __nv_bfloat16* Blo = reinterpret_cast<__nv_bfloat16*>(smem + K3_OFF_BLO);
    int l0 = blockIdx.x * 64;
    int d0 = blockIdx.y * 128;
    int b = blockIdx.z;
    int tid = threadIdx.x;
    int wid = tid >> 5;
    int wm = (wid >> 1) * 32;            // d
    int wn = (wid & 1) * 32;             // l

    // A: h tile 128d x 64s
    const __nv_bfloat16* hh = g_h_hi + ((size_t)b * DM2 + d0) * SS;
    const __nv_bfloat16* hl = g_h_lo + ((size_t)b * DM2 + d0) * SS;
#pragma unroll
    for (int k = 0; k < 8; k++) {
        int e = tid + k * 256;
        int d = e >> 4, q = e & 15;
        *reinterpret_cast<uint2*>(&Ahi[d * K3_ALD + q * 4]) =
            *reinterpret_cast<const uint2*>(&hh[d * SS + q * 4]);
        *reinterpret_cast<uint2*>(&Alo[d * K3_ALD + q * 4]) =
            *reinterpret_cast<const uint2*>(&hl[d * SS + q * 4]);
    }
    // B: conv tile 64s x 64l (row-major [k=s][n=l])
#pragma unroll
    for (int k = 0; k < 4; k++) {
        int e = tid + k * 256;
        int si = e >> 4, q = e & 15;
        size_t src = (((size_t)b * SS + si) << 12) + l0 + q * 4;
        *reinterpret_cast<uint2*>(&Bhi[si * K3_BLD + q * 4]) =
            *reinterpret_cast<const uint2*>(&g_conv_hi[src]);
        *reinterpret_cast<uint2*>(&Blo[si * K3_BLD + q * 4]) =
            *reinterpret_cast<const uint2*>(&g_conv_lo[src]);
    }
    __syncthreads();

    wmma::fragment<wmma::accumulator, 16, 16, 16, float> acc[2][2];
#pragma unroll
    for (int i = 0; i < 2; i++)
#pragma unroll
        for (int j = 0; j < 2; j++) wmma::fill_fragment(acc[i][j], 0.f);

#pragma unroll
    for (int ks = 0; ks < 4; ks++) {
        int kk = ks * 16;
        wmma::fragment<wmma::matrix_a, 16, 16, 16, __nv_bfloat16, wmma::row_major> ah[2], al[2];
        wmma::fragment<wmma::matrix_b, 16, 16, 16, __nv_bfloat16, wmma::row_major> bh[2], bl[2];
#pragma unroll
        for (int i = 0; i < 2; i++) {
            wmma::load_matrix_sync(ah[i], Ahi + (wm + i * 16) * K3_ALD + kk, K3_ALD);
            wmma::load_matrix_sync(al[i], Alo + (wm + i * 16) * K3_ALD + kk, K3_ALD);
        }
#pragma unroll
        for (int j = 0; j < 2; j++) {
            wmma::load_matrix_sync(bh[j], Bhi + kk * K3_BLD + wn + j * 16, K3_BLD);
            wmma::load_matrix_sync(bl[j], Blo + kk * K3_BLD + wn + j * 16, K3_BLD);
        }
#pragma unroll
        for (int i = 0; i < 2; i++)
#pragma unroll
            for (int j = 0; j < 2; j++) {
                wmma::mma_sync(acc[i][j], ah[i], bh[j], acc[i][j]);
                wmma::mma_sync(acc[i][j], ah[i], bl[j], acc[i][j]);
                wmma::mma_sync(acc[i][j], al[i], bh[j], acc[i][j]);
            }
    }
    __syncthreads();
    float* stage = reinterpret_cast<float*>(smem);          // [128][72]
#pragma unroll
    for (int i = 0; i < 2; i++)
#pragma unroll
        for (int j = 0; j < 2; j++)
            wmma::store_matrix_sync(stage + (wm + i * 16) * K3_ALD + wn + j * 16,
                                    acc[i][j], K3_ALD, wmma::mem_row_major);
    __syncthreads();
#pragma unroll
    for (int k = 0; k < 8; k++) {
        int g = tid + k * 256;               // 2048 f4 = 128 rows x 16
        int row = g >> 4, c4 = g & 15;
        float4 v = *reinterpret_cast<const float4*>(&stage[row * K3_ALD + c4 * 4]);
        *reinterpret_cast<float4*>(
            &g_ypre[((size_t)b * DM2 + d0 + row) * LSZ + l0 + c4 * 4]) = v;
    }
}

// ============================================================
// k4b: final depthwise conv over 1024 channels.
// ============================================================
__global__ void k4b_conv(const float* __restrict__ x,
                         const float* __restrict__ wDW,
                         const float* __restrict__ bDW,
                         float* __restrict__ out) {
    __shared__ float sm[66][68];
    int c = blockIdx.x, b = blockIdx.y;
    int tid = threadIdx.x;
    const float* plane = (c < DM2)
        ? (g_ypre + ((size_t)b * DM2 + c) * LSZ)
        : (x + ((size_t)b * DMODEL + c) * LSZ);

    for (int e = tid; e < 66 * 68; e += 256) ((float*)sm)[e] = 0.f;
    __syncthreads();
#pragma unroll
    for (int k = 0; k < 16; k++) {
        int idx = tid + k * 256;
        sm[(idx >> 6) + 1][(idx & 63) + 1] = plane[idx];
    }
    __syncthreads();

    float w[9];
#pragma unroll
    for (int i = 0; i < 9; i++) w[i] = wDW[c * 9 + i];
    float bb = bDW[c];
    float* ob = out + ((size_t)b * DMODEL + c) * LSZ;
#pragma unroll
    for (int k = 0; k < 16; k++) {
        int idx = tid + k * 256;
        int r = idx >> 6, cc = idx & 63;
        float acc = bb;
#pragma unroll
        for (int i = 0; i < 3; i++)
#pragma unroll
            for (int j = 0; j < 3; j++)
                acc += w[i * 3 + j] * sm[r + i][cc + j];
        ob[idx] = acc;
    }
}

// ============================================================
extern "C" void kernel_launch(void* const* d_in, const int* in_sizes, int n_in,
                              void* d_out, int out_size) {
    const float* x      = (const float*)d_in[0];
    const float* w_bcdt = (const float*)d_in[1];
    const float* b_bcdt = (const float*)d_in[2];
    const float* w_dw   = (const float*)d_in[3];
    const float* b_dw   = (const float*)d_in[4];
    const float* A      = (const float*)d_in[5];
    const float* coeffs = (const float*)d_in[6];
    const float* w_DW   = (const float*)d_in[7];
    const float* b_DW   = (const float*)d_in[8];

    float* y_out = (float*)d_out;                          // (16,1024,4096)
    float* h_out = y_out + (size_t)BATCH * DMODEL * LSZ;   // (16,512,64)

    cudaFuncSetAttribute(k1_wmma, cudaFuncAttributeMaxDynamicSharedMemorySize, K1_SMEM);
    cudaFuncSetAttribute(k3_wmma, cudaFuncAttributeMaxDynamicSharedMemorySize, K3_SMEM);
    cudaFuncSetAttribute(k4a_wmma, cudaFuncAttributeMaxDynamicSharedMemorySize, K3_SMEM);

    cudaMemsetAsync(h_out, 0, (size_t)BATCH * DM2 * SS * sizeof(float));

    k0_convert_x<<<2048, 256>>>((const float4*)x);
    k0_convert_w<<<8, 256>>>((const float4*)w_bcdt);
    k1_wmma<<<dim3(32, 16), 256, K1_SMEM>>>(b_bcdt);
    k2_conv_softmax<<<dim3(64, 16), 256>>>(w_dw, b_dw, A, coeffs);
    k3_wmma<<<dim3(4, 4, 16), 256, K3_SMEM>>>(h_out);
    k3b_convert_h<<<128, 256>>>((const float4*)h_out, coeffs);
    k4a_wmma<<<dim3(64, 4, 16), 256, K3_SMEM>>>();
    k4b_conv<<<dim3(1024, 16), 256>>>(x, w_DW, b_DW, y_out);
}

// round 6
// speedup vs baseline: 1.6765x; 1.0364x over previous
#include <cuda_runtime.h>
#include <cuda_bf16.h>
#include <mma.h>
#include <cstdint>

using namespace nvcuda;

#define BATCH 16
#define DMODEL 1024
#define DM2 512
#define LSZ 4096
#define SS 64

// ---- scratch (device globals; no allocations allowed) ----
__device__ float g_bcdt[BATCH * SS * LSZ];                 // 16 MB fp32
__device__ __nv_bfloat16 g_conv_hi[BATCH * SS * LSZ];      // 8 MB
__device__ __nv_bfloat16 g_conv_lo[BATCH * SS * LSZ];
__device__ __nv_bfloat16 g_AB_hi[BATCH * SS * LSZ];
__device__ __nv_bfloat16 g_AB_lo[BATCH * SS * LSZ];
__device__ __nv_bfloat16 g_xh_hi[BATCH * DM2 * LSZ];       // 64 MB
__device__ __nv_bfloat16 g_xh_lo[BATCH * DM2 * LSZ];
__device__ __nv_bfloat16 g_w_hi[SS * DM2];
__device__ __nv_bfloat16 g_w_lo[SS * DM2];
__device__ __nv_bfloat16 g_h_hi[BATCH * DM2 * SS];         // c1-scaled
__device__ __nv_bfloat16 g_h_lo[BATCH * DM2 * SS];
__device__ float g_ypre[BATCH * DM2 * LSZ];                // 128 MB

__device__ __forceinline__ uint32_t pk(__nv_bfloat16 a, __nv_bfloat16 b) {
    __nv_bfloat162 t; t.x = a; t.y = b;
    return *reinterpret_cast<uint32_t*>(&t);
}
__device__ __forceinline__ void split1(float v, __nv_bfloat16& hi, __nv_bfloat16& lo) {
    hi = __float2bfloat16_rn(v);
    lo = __float2bfloat16_rn(v - __bfloat162float(hi));
}

// ============================================================
// k0: xh (first 512 rows of x) -> bf16 hi/lo. 8 floats/thread,
// 16B packed stores. 4.19M 8-float groups.
// ============================================================
__global__ void k0_convert_x(const float4* __restrict__ x4) {
    int tid = threadIdx.x;
#pragma unroll
    for (int k = 0; k < 8; k++) {
        int u = blockIdx.x * 2048 + k * 256 + tid;          // 8-float group idx
        size_t src = ((size_t)(u >> 18) << 20) + (size_t)(u & 0x3FFFF) * 2;
        float4 v0 = x4[src], v1 = x4[src + 1];
        __nv_bfloat16 h[8], l[8];
        split1(v0.x, h[0], l[0]); split1(v0.y, h[1], l[1]);
        split1(v0.z, h[2], l[2]); split1(v0.w, h[3], l[3]);
        split1(v1.x, h[4], l[4]); split1(v1.y, h[5], l[5]);
        split1(v1.z, h[6], l[6]); split1(v1.w, h[7], l[7]);
        uint4 hv = make_uint4(pk(h[0], h[1]), pk(h[2], h[3]), pk(h[4], h[5]), pk(h[6], h[7]));
        uint4 lv = make_uint4(pk(l[0], l[1]), pk(l[2], l[3]), pk(l[4], l[5]), pk(l[6], l[7]));
        *reinterpret_cast<uint4*>(&g_xh_hi[(size_t)u * 8]) = hv;
        *reinterpret_cast<uint4*>(&g_xh_lo[(size_t)u * 8]) = lv;
    }
}
__global__ void k0_convert_w(const float4* __restrict__ w4) {
    int tid = threadIdx.x;
#pragma unroll
    for (int k = 0; k < 4; k++) {
        int g = blockIdx.x * 1024 + k * 256 + tid;          // 8192 f4
        float4 v = w4[g];
        __nv_bfloat16 h0, l0, h1, l1, h2, l2, h3, l3;
        split1(v.x, h0, l0); split1(v.y, h1, l1);
        split1(v.z, h2, l2); split1(v.w, h3, l3);
        *reinterpret_cast<uint2*>(&g_w_hi[g * 4]) = make_uint2(pk(h0, h1), pk(h2, h3));
        *reinterpret_cast<uint2*>(&g_w_lo[g * 4]) = make_uint2(pk(l0, l1), pk(l2, l3));
    }
}

// ============================================================
// k1 (wmma): BCdt[s,l] = sum_d w[s,d]*xh[d,l] + bias[s]
// ============================================================
#define K1_WLD 72
#define K1_XLD 136
#define K1_OFF_WHI 0
#define K1_OFF_WLO 9216
#define K1_OFF_XHI 18432
#define K1_OFF_XLO 35840
#define K1_SMEM 53248

__global__ void k1_wmma(const float* __restrict__ bias) {
    extern __shared__ __align__(16) char smem[];
    __nv_bfloat16* Whi = reinterpret_cast<__nv_bfloat16*>(smem + K1_OFF_WHI);
    __nv_bfloat16* Wlo = reinterpret_cast<__nv_bfloat16*>(smem + K1_OFF_WLO);
    __nv_bfloat16* Xhi = reinterpret_cast<__nv_bfloat16*>(smem + K1_OFF_XHI);
    __nv_bfloat16* Xlo = reinterpret_cast<__nv_bfloat16*>(smem + K1_OFF_XLO);
    int b = blockIdx.y;
    int l0 = blockIdx.x * 128;
    int tid = threadIdx.x;
    int wid = tid >> 5;
    int wm = (wid >> 1) * 16;    // s
    int wn = (wid & 1) * 64;     // l

    wmma::fragment<wmma::accumulator, 16, 16, 16, float> acc[4];
#pragma unroll
    for (int j = 0; j < 4; j++) wmma::fill_fragment(acc[j], 0.f);

    for (int kc = 0; kc < DM2; kc += 64) {
#pragma unroll
        for (int k = 0; k < 4; k++) {
            int e = tid + k * 256;
            int s = e >> 4, q = e & 15;
            *reinterpret_cast<uint2*>(&Whi[s * K1_WLD + q * 4]) =
                *reinterpret_cast<const uint2*>(&g_w_hi[s * DM2 + kc + q * 4]);
            *reinterpret_cast<uint2*>(&Wlo[s * K1_WLD + q * 4]) =
                *reinterpret_cast<const uint2*>(&g_w_lo[s * DM2 + kc + q * 4]);
        }
#pragma unroll
        for (int k = 0; k < 8; k++) {
            int e = tid + k * 256;
            int r = e >> 5, q = e & 31;
            size_t src = (((size_t)b * DM2 + kc + r) << 12) + l0 + q * 4;
            *reinterpret_cast<uint2*>(&Xhi[r * K1_XLD + q * 4]) =
                *reinterpret_cast<const uint2*>(&g_xh_hi[src]);
            *reinterpret_cast<uint2*>(&Xlo[r * K1_XLD + q * 4]) =
                *reinterpret_cast<const uint2*>(&g_xh_lo[src]);
        }
        __syncthreads();
#pragma unroll
        for (int ks = 0; ks < 4; ks++) {
            int kk = ks * 16;
            wmma::fragment<wmma::matrix_a, 16, 16, 16, __nv_bfloat16, wmma::row_major> ah, al;
            wmma::load_matrix_sync(ah, Whi + wm * K1_WLD + kk, K1_WLD);
            wmma::load_matrix_sync(al, Wlo + wm * K1_WLD + kk, K1_WLD);
#pragma unroll
            for (int j = 0; j < 4; j++) {
                wmma::fragment<wmma::matrix_b, 16, 16, 16, __nv_bfloat16, wmma::row_major> bh, bl;
                wmma::load_matrix_sync(bh, Xhi + kk * K1_XLD + wn + j * 16, K1_XLD);
                wmma::load_matrix_sync(bl, Xlo + kk * K1_XLD + wn + j * 16, K1_XLD);
                wmma::mma_sync(acc[j], ah, bh, acc[j]);
                wmma::mma_sync(acc[j], ah, bl, acc[j]);
                wmma::mma_sync(acc[j], al, bh, acc[j]);
            }
        }
        __syncthreads();
    }
    float* stage = reinterpret_cast<float*>(smem);          // [64][136]
#pragma unroll
    for (int j = 0; j < 4; j++)
        wmma::store_matrix_sync(stage + wm * K1_XLD + wn + j * 16, acc[j],
                                K1_XLD, wmma::mem_row_major);
    __syncthreads();
#pragma unroll
    for (int k = 0; k < 8; k++) {
        int g = tid + k * 256;              // 2048 f4 = 64 rows x 32
        int row = g >> 5, c4 = g & 31;
        float bv = bias[row];
        float4 v = *reinterpret_cast<const float4*>(&stage[row * K1_XLD + c4 * 4]);
        v.x += bv; v.y += bv; v.z += bv; v.w += bv;
        *reinterpret_cast<float4*>(
            &g_bcdt[((size_t)b * SS + row) * LSZ + l0 + c4 * 4]) = v;
    }
}

// ============================================================
// k2: conv3x3 + softmax; writes bf16 hi/lo of conv and AB.
// ============================================================
__global__ void k2_conv_softmax(const float* __restrict__ wdw,
                                const float* __restrict__ bdw,
                                const float* __restrict__ A,
                                const float* __restrict__ coeffs) {
    __shared__ float sm[66][68];
    __shared__ float red[8];
    int s = blockIdx.x, b = blockIdx.y;
    int tid = threadIdx.x;
    size_t off = ((size_t)b * SS + s) * LSZ;
    const float* plane = g_bcdt + off;

    for (int e = tid; e < 66 * 68; e += 256) ((float*)sm)[e] = 0.f;
    __syncthreads();
#pragma unroll
    for (int k = 0; k < 16; k++) {
        int idx = tid + k * 256;
        sm[(idx >> 6) + 1][(idx & 63) + 1] = plane[idx];
    }
    __syncthreads();

    float w[9];
#pragma unroll
    for (int i = 0; i < 9; i++) w[i] = wdw[s * 9 + i];
    float bb = bdw[s];
    float c0 = coeffs[0], c2 = coeffs[2];
    float Av = A[s];

    float v[16];
    float lmax = -1e30f;
#pragma unroll
    for (int k = 0; k < 8; k++) {
        int base = tid * 2 + k * 512;       // even; pair stays in one row
        int r = base >> 6, c = base & 63;
        float a0 = bb, a1 = bb;
#pragma unroll
        for (int i = 0; i < 3; i++)
#pragma unroll
            for (int j = 0; j < 3; j++) {
                float wv = w[i * 3 + j];
                a0 += wv * sm[r + i][c + j];
                a1 += wv * sm[r + i][c + 1 + j];
            }
        v[2 * k] = a0; v[2 * k + 1] = a1;
        lmax = fmaxf(lmax, fmaxf(c2 * a0, c2 * a1) + Av);
    }
#pragma unroll
    for (int o = 16; o > 0; o >>= 1)
        lmax = fmaxf(lmax, __shfl_xor_sync(0xffffffffu, lmax, o));
    if ((tid & 31) == 0) red[tid >> 5] = lmax;
    __syncthreads();
    float bmax = red[0];
#pragma unroll
    for (int i = 1; i < 8; i++) bmax = fmaxf(bmax, red[i]);
    __syncthreads();

    float ev[16];
    float lsum = 0.f;
#pragma unroll
    for (int k = 0; k < 16; k++) {
        ev[k] = __expf(c2 * v[k] + Av - bmax);
        lsum += ev[k];
    }
#pragma unroll
    for (int o = 16; o > 0; o >>= 1)
        lsum += __shfl_xor_sync(0xffffffffu, lsum, o);
    if ((tid & 31) == 0) red[tid >> 5] = lsum;
    __syncthreads();
    float bsum = 0.f;
#pragma unroll
    for (int i = 0; i < 8; i++) bsum += red[i];
    float inv = 1.f / bsum;

#pragma unroll
    for (int k = 0; k < 8; k++) {
        int base = tid * 2 + k * 512;
        float v0 = v[2 * k], v1 = v[2 * k + 1];
        __nv_bfloat16 ch0, cl0, ch1, cl1;
        split1(v0, ch0, cl0); split1(v1, ch1, cl1);
        *reinterpret_cast<uint32_t*>(&g_conv_hi[off + base]) = pk(ch0, ch1);
        *reinterpret_cast<uint32_t*>(&g_conv_lo[off + base]) = pk(cl0, cl1);
        float a0 = ev[2 * k] * inv * c0 * v0;
        float a1 = ev[2 * k + 1] * inv * c0 * v1;
        __nv_bfloat16 ah0, al0, ah1, al1;
        split1(a0, ah0, al0); split1(a1, ah1, al1);
        *reinterpret_cast<uint32_t*>(&g_AB_hi[off + base]) = pk(ah0, ah1);
        *reinterpret_cast<uint32_t*>(&g_AB_lo[off + base]) = pk(al0, al1);
    }
}

// ============================================================
// k3 (wmma): h[d,s] = sum_l xh[d,l]*AB[s,l]
// ============================================================
#define K3_ALD 72
#define K3_BLD 72
#define K3_OFF_AHI 0
#define K3_OFF_ALO 18432
#define K3_OFF_BHI 36864
#define K3_OFF_BLO 46080
#define K3_SMEM 55296

__global__ void k3_wmma(float* __restrict__ hout) {
    extern __shared__ __align__(16) char smem[];
    __nv_bfloat16* Ahi = reinterpret_cast<__nv_bfloat16*>(smem + K3_OFF_AHI);
    __nv_bfloat16* Alo = reinterpret_cast<__nv_bfloat16*>(smem + K3_OFF_ALO);
    __nv_bfloat16* Bhi = reinterpret_cast<__nv_bfloat16*>(smem + K3_OFF_BHI);
    __nv_bfloat16* Blo = reinterpret_cast<__nv_bfloat16*>(smem + K3_OFF_BLO);
    int lp = blockIdx.x;                 // 0..3
    int d0 = blockIdx.y * 128;
    int b = blockIdx.z;
    int tid = threadIdx.x;
    int wid = tid >> 5;
    int wm = (wid >> 1) * 32;            // d
    int wn = (wid & 1) * 32;             // s

    wmma::fragment<wmma::accumulator, 16, 16, 16, float> acc[2][2];
#pragma unroll
    for (int i = 0; i < 2; i++)
#pragma unroll
        for (int j = 0; j < 2; j++) wmma::fill_fragment(acc[i][j], 0.f);

    for (int lc = 0; lc < 1024; lc += 64) {
        int lbase = lp * 1024 + lc;
#pragma unroll
        for (int k = 0; k < 8; k++) {        // A: 128d x 64l
            int e = tid + k * 256;
            int d = e >> 4, q = e & 15;
            size_t src = (((size_t)b * DM2 + d0 + d) << 12) + lbase + q * 4;
            *reinterpret_cast<uint2*>(&Ahi[d * K3_ALD + q * 4]) =
                *reinterpret_cast<const uint2*>(&g_xh_hi[src]);
            *reinterpret_cast<uint2*>(&Alo[d * K3_ALD + q * 4]) =
                *reinterpret_cast<const uint2*>(&g_xh_lo[src]);
        }
#pragma unroll
        for (int k = 0; k < 4; k++) {        // B: 64s x 64l
            int e = tid + k * 256;
            int si = e >> 4, q = e & 15;
            size_t src = (((size_t)b * SS + si) << 12) + lbase + q * 4;
            *reinterpret_cast<uint2*>(&Bhi[si * K3_BLD + q * 4]) =
                *reinterpret_cast<const uint2*>(&g_AB_hi[src]);
            *reinterpret_cast<uint2*>(&Blo[si * K3_BLD + q * 4]) =
                *reinterpret_cast<const uint2*>(&g_AB_lo[src]);
        }
        __syncthreads();
#pragma unroll
        for (int ks = 0; ks < 4; ks++) {
            int kk = ks * 16;
            wmma::fragment<wmma::matrix_a, 16, 16, 16, __nv_bfloat16, wmma::row_major> ah[2], al[2];
            wmma::fragment<wmma::matrix_b, 16, 16, 16, __nv_bfloat16, wmma::col_major> bh[2], bl[2];
#pragma unroll
            for (int i = 0; i < 2; i++) {
                wmma::load_matrix_sync(ah[i], Ahi + (wm + i * 16) * K3_ALD + kk, K3_ALD);
                wmma::load_matrix_sync(al[i], Alo + (wm + i * 16) * K3_ALD + kk, K3_ALD);
            }
#pragma unroll
            for (int j = 0; j < 2; j++) {
                wmma::load_matrix_sync(bh[j], Bhi + (wn + j * 16) * K3_BLD + kk, K3_BLD);
                wmma::load_matrix_sync(bl[j], Blo + (wn + j * 16) * K3_BLD + kk, K3_BLD);
            }
#pragma unroll
            for (int i = 0; i < 2; i++)
#pragma unroll
                for (int j = 0; j < 2; j++) {
                    wmma::mma_sync(acc[i][j], ah[i], bh[j], acc[i][j]);
                    wmma::mma_sync(acc[i][j], ah[i], bl[j], acc[i][j]);
                    wmma::mma_sync(acc[i][j], al[i], bh[j], acc[i][j]);
                }
        }
        __syncthreads();
    }
    float* stage = reinterpret_cast<float*>(smem);          // [128][72]
#pragma unroll
    for (int i = 0; i < 2; i++)
#pragma unroll
        for (int j = 0; j < 2; j++)
            wmma::store_matrix_sync(stage + (wm + i * 16) * K3_ALD + wn + j * 16,
                                    acc[i][j], K3_ALD, wmma::mem_row_major);
    __syncthreads();
    float* hb = hout + ((size_t)b * DM2 + d0) * SS;
#pragma unroll
    for (int k = 0; k < 32; k++) {
        int e = tid + k * 256;               // 8192 = 128d x 64s
        int d = e >> 6, si = e & 63;
        atomicAdd(&hb[d * SS + si], stage[d * K3_ALD + si]);
    }
}

// ============================================================
// k3b: h fp32 -> bf16 hi/lo with c1 folded in.
// ============================================================
__global__ void k3b_convert_h(const float4* __restrict__ h4,
                              const float* __restrict__ coeffs) {
    float c1 = coeffs[1];
    int tid = threadIdx.x;
#pragma unroll
    for (int k = 0; k < 4; k++) {
        int g = blockIdx.x * 1024 + k * 256 + tid;
        float4 v = h4[g];
        v.x *= c1; v.y *= c1; v.z *= c1; v.w *= c1;
        __nv_bfloat16 h0, l0, h1, l1, h2, l2, h3, l3;
        split1(v.x, h0, l0); split1(v.y, h1, l1);
        split1(v.z, h2, l2); split1(v.w, h3, l3);
        *reinterpret_cast<uint2*>(&g_h_hi[(size_t)g * 4]) = make_uint2(pk(h0, h1), pk(h2, h3));
        *reinterpret_cast<uint2*>(&g_h_lo[(size_t)g * 4]) = make_uint2(pk(l0, l1), pk(l2, l3));
    }
}

// ============================================================
// k4a (wmma): y_pre[d,l] = sum_s (c1*h)[d,s]*conv[s,l]
// ============================================================
__global__ void k4a_wmma() {
    extern __shared__ __align__(16) char smem[];
    __nv_bfloat16* Ahi = reinterpret_cast<__nv_bfloat16*>(smem + K3_OFF_AHI);
    __nv_bfloat16* Alo = reinterpret_cast<__nv_bfloat16*>(smem + K3_OFF_ALO);
    __nv_bfloat16* Bhi = reinterpret_cast<__nv_bfloat16*>(smem + K3_OFF_BHI);
    __nv_bfloat16* Blo = reinterpret_cast<__nv_bfloat16*>(smem + K3_OFF_BLO);
    int l0 = blockIdx.x * 64;
    int d0 = blockIdx.y * 128;
    int b = blockIdx.z;
    int tid = threadIdx.x;
    int wid = tid >> 5;
    int wm = (wid >> 1) * 32;            // d
    int wn = (wid & 1) * 32;             // l

    const __nv_bfloat16* hh = g_h_hi + ((size_t)b * DM2 + d0) * SS;
    const __nv_bfloat16* hl = g_h_lo + ((size_t)b * DM2 + d0) * SS;
#pragma unroll
    for (int k = 0; k < 8; k++) {
        int e = tid + k * 256;
        int d = e >> 4, q = e & 15;
        *reinterpret_cast<uint2*>(&Ahi[d * K3_ALD + q * 4]) =
            *reinterpret_cast<const uint2*>(&hh[d * SS + q * 4]);
        *reinterpret_cast<uint2*>(&Alo[d * K3_ALD + q * 4]) =
            *reinterpret_cast<const uint2*>(&hl[d * SS + q * 4]);
    }
#pragma unroll
    for (int k = 0; k < 4; k++) {
        int e = tid + k * 256;
        int si = e >> 4, q = e & 15;
        size_t src = (((size_t)b * SS + si) << 12) + l0 + q * 4;
        *reinterpret_cast<uint2*>(&Bhi[si * K3_BLD + q * 4]) =
            *reinterpret_cast<const uint2*>(&g_conv_hi[src]);
        *reinterpret_cast<uint2*>(&Blo[si * K3_BLD + q * 4]) =
            *reinterpret_cast<const uint2*>(&g_conv_lo[src]);
    }
    __syncthreads();

    wmma::fragment<wmma::accumulator, 16, 16, 16, float> acc[2][2];
#pragma unroll
    for (int i = 0; i < 2; i++)
#pragma unroll
        for (int j = 0; j < 2; j++) wmma::fill_fragment(acc[i][j], 0.f);

#pragma unroll
    for (int ks = 0; ks < 4; ks++) {
        int kk = ks * 16;
        wmma::fragment<wmma::matrix_a, 16, 16, 16, __nv_bfloat16, wmma::row_major> ah[2], al[2];
        wmma::fragment<wmma::matrix_b, 16, 16, 16, __nv_bfloat16, wmma::row_major> bh[2], bl[2];
#pragma unroll
        for (int i = 0; i < 2; i++) {
            wmma::load_matrix_sync(ah[i], Ahi + (wm + i * 16) * K3_ALD + kk, K3_ALD);
            wmma::load_matrix_sync(al[i], Alo + (wm + i * 16) * K3_ALD + kk, K3_ALD);
        }
#pragma unroll
        for (int j = 0; j < 2; j++) {
            wmma::load_matrix_sync(bh[j], Bhi + kk * K3_BLD + wn + j * 16, K3_BLD);
            wmma::load_matrix_sync(bl[j], Blo + kk * K3_BLD + wn + j * 16, K3_BLD);
        }
#pragma unroll
        for (int i = 0; i < 2; i++)
#pragma unroll
            for (int j = 0; j < 2; j++) {
                wmma::mma_sync(acc[i][j], ah[i], bh[j], acc[i][j]);
                wmma::mma_sync(acc[i][j], ah[i], bl[j], acc[i][j]);
                wmma::mma_sync(acc[i][j], al[i], bh[j], acc[i][j]);
            }
    }
    __syncthreads();
    float* stage = reinterpret_cast<float*>(smem);          // [128][72]
#pragma unroll
    for (int i = 0; i < 2; i++)
#pragma unroll
        for (int j = 0; j < 2; j++)
            wmma::store_matrix_sync(stage + (wm + i * 16) * K3_ALD + wn + j * 16,
                                    acc[i][j], K3_ALD, wmma::mem_row_major);
    __syncthreads();
#pragma unroll
    for (int k = 0; k < 8; k++) {
        int g = tid + k * 256;               // 2048 f4 = 128 rows x 16
        int row = g >> 4, c4 = g & 15;
        float4 v = *reinterpret_cast<const float4*>(&stage[row * K3_ALD + c4 * 4]);
        *reinterpret_cast<float4*>(
            &g_ypre[((size_t)b * DM2 + d0 + row) * LSZ + l0 + c4 * 4]) = v;
    }
}

// ============================================================
// k4b: final depthwise conv, float4 I/O.
// smem: rows 0..65 (64 data rows + halo), stride 72, data cols 4..67.
// ============================================================
__global__ void k4b_conv(const float* __restrict__ x,
                         const float* __restrict__ wDW,
                         const float* __restrict__ bDW,
                         float* __restrict__ out) {
    __shared__ __align__(16) float sm[66][72];
    int c = blockIdx.x, b = blockIdx.y;
    int tid = threadIdx.x;
    const float* plane = (c < DM2)
        ? (g_ypre + ((size_t)b * DM2 + c) * LSZ)
        : (x + ((size_t)b * DMODEL + c) * LSZ);
    const float4* plane4 = reinterpret_cast<const float4*>(plane);

    // zero halo cells only
    if (tid < 72) { sm[0][tid] = 0.f; sm[65][tid] = 0.f; }
    else if (tid < 136) { int r = tid - 72 + 1; sm[r][3] = 0.f; sm[r][68] = 0.f; }
    // fill: 1024 float4, 4 per thread, 16B-aligned smem stores
#pragma unroll
    for (int k = 0; k < 4; k++) {
        int g = tid + k * 256;
        int row = g >> 4, cq = g & 15;
        *reinterpret_cast<float4*>(&sm[row + 1][4 + cq * 4]) = plane4[g];
    }
    __syncthreads();

    float w[9];
#pragma unroll
    for (int i = 0; i < 9; i++) w[i] = wDW[c * 9 + i];
    float bb = bDW[c];
    float4* ob4 = reinterpret_cast<float4*>(out + ((size_t)b * DMODEL + c) * LSZ);
#pragma unroll
    for (int k = 0; k < 4; k++) {
        int g = tid + k * 256;
        int row = g >> 4, c0 = (g & 15) * 4;
        float o[4];
#pragma unroll
        for (int u = 0; u < 4; u++) {
            int cc = c0 + u;
            float acc = bb;
#pragma unroll
            for (int i = 0; i < 3; i++)
#pragma unroll
                for (int j = 0; j < 3; j++)
                    acc += w[i * 3 + j] * sm[row + i][3 + cc + j];
            o[u] = acc;
        }
        ob4[g] = make_float4(o[0], o[1], o[2], o[3]);
    }
}

// ============================================================
extern "C" void kernel_launch(void* const* d_in, const int* in_sizes, int n_in,
                              void* d_out, int out_size) {
    const float* x      = (const float*)d_in[0];
    const float* w_bcdt = (const float*)d_in[1];
    const float* b_bcdt = (const float*)d_in[2];
    const float* w_dw   = (const float*)d_in[3];
    const float* b_dw   = (const float*)d_in[4];
    const float* A      = (const float*)d_in[5];
    const float* coeffs = (const float*)d_in[6];
    const float* w_DW   = (const float*)d_in[7];
    const float* b_DW   = (const float*)d_in[8];

    float* y_out = (float*)d_out;                          // (16,1024,4096)
    float* h_out = y_out + (size_t)BATCH * DMODEL * LSZ;   // (16,512,64)

    cudaFuncSetAttribute(k1_wmma, cudaFuncAttributeMaxDynamicSharedMemorySize, K1_SMEM);
    cudaFuncSetAttribute(k3_wmma, cudaFuncAttributeMaxDynamicSharedMemorySize, K3_SMEM);
    cudaFuncSetAttribute(k4a_wmma, cudaFuncAttributeMaxDynamicSharedMemorySize, K3_SMEM);

    cudaMemsetAsync(h_out, 0, (size_t)BATCH * DM2 * SS * sizeof(float));

    k0_convert_x<<<2048, 256>>>((const float4*)x);
    k0_convert_w<<<8, 256>>>((const float4*)w_bcdt);
    k1_wmma<<<dim3(32, 16), 256, K1_SMEM>>>(b_bcdt);
    k2_conv_softmax<<<dim3(64, 16), 256>>>(w_dw, b_dw, A, coeffs);
    k3_wmma<<<dim3(4, 4, 16), 256, K3_SMEM>>>(h_out);
    k3b_convert_h<<<128, 256>>>((const float4*)h_out, coeffs);
    k4a_wmma<<<dim3(64, 4, 16), 256, K3_SMEM>>>();
    k4b_conv<<<dim3(1024, 16), 256>>>(x, w_DW, b_DW, y_out);
}